// round 14
// baseline (speedup 1.0000x reference)
#include <cuda_runtime.h>
#include <cuda_fp16.h>
#include <cstdint>

#define B_    8
#define LQ    4096
#define LK    4096
#define D_    512
#define LSEL  2744
#define MPAD  2816
#define SCALE 0.04419417382415922f   // 1/sqrt(512)

// ============================ device scratch ================================
__device__ __half g_qh[B_ * LQ * D_];           // Q*SCALE fp16
__device__ __half g_kh[B_ * LK * D_];           // K fp16
__device__ __half g_vth[B_ * D_ * LK];          // V^T fp16 [b][d][k]
__device__ __half g_E[(size_t)B_ * MPAD * LK];  // exp(S) fp16 [b][m][k]
__device__ __half g_kt[(size_t)B_ * D_ * LK];   // K^T fp16 [b][d][k]
__device__ float  g_Zpart[B_ * MPAD * 32];
__device__ float  g_kreduce[B_ * D_];
__device__ double g_meanpart[B_ * 128 * D_];
__device__ float  g_meanvals[B_ * D_];
__device__ float  g_sqk[B_ * LQ];
__device__ float  g_thresh[B_];
__device__ int    g_selidx[B_ * LSEL];
__device__ int    g_selcnt[B_];

// ============================ PTX helpers ===================================
__device__ __forceinline__ uint32_t smem_u32(const void* p) {
    uint32_t a;
    asm("{ .reg .u64 t; cvta.to.shared.u64 t, %1; cvt.u32.u64 %0, t; }" : "=r"(a) : "l"(p));
    return a;
}

#define CP_ASYNC16(dst, src) \
    asm volatile("cp.async.cg.shared.global [%0], [%1], 16;" :: "r"(dst), "l"(src) : "memory")
#define CP_COMMIT() asm volatile("cp.async.commit_group;" ::: "memory")
#define CP_WAIT2()  asm volatile("cp.async.wait_group 2;" ::: "memory")
#define CP_WAIT0()  asm volatile("cp.async.wait_group 0;" ::: "memory")

#define LDSM4(r, a) \
    asm volatile("ldmatrix.sync.aligned.m8n8.x4.shared.b16 {%0,%1,%2,%3}, [%4];" \
        : "=r"((r)[0]), "=r"((r)[1]), "=r"((r)[2]), "=r"((r)[3]) : "r"(a))

#define MMAH(d, a, b0, b1) \
    asm volatile("mma.sync.aligned.m16n8k16.row.col.f32.f16.f16.f32 " \
        "{%0,%1,%2,%3}, {%4,%5,%6,%7}, {%8,%9}, {%0,%1,%2,%3};" \
        : "+f"((d)[0]), "+f"((d)[1]), "+f"((d)[2]), "+f"((d)[3]) \
        : "r"((a)[0]), "r"((a)[1]), "r"((a)[2]), "r"((a)[3]), "r"(b0), "r"(b1))

// swizzled addr inside one tile of 128-byte rows (SW128)
__device__ __forceinline__ uint32_t swaddr(uint32_t base, int row, int kb) {
    uint32_t o = (uint32_t)(row * 128 + kb);
    return base + (o ^ ((o >> 3) & 0x70));
}

__device__ __forceinline__ unsigned f2sort(float f) {
    unsigned u = __float_as_uint(f);
    return (u & 0x80000000u) ? ~u : (u | 0x80000000u);
}
__device__ __forceinline__ float sort2f(unsigned u) {
    unsigned fb = (u & 0x80000000u) ? (u ^ 0x80000000u) : ~u;
    return __uint_as_float(fb);
}
__device__ __forceinline__ unsigned h2sort(unsigned hbits) {
    return (hbits & 0x8000u) ? (0xFFFFu & ~hbits) : (hbits | 0x8000u);
}
// sortable-u16 -> exact fixed-point (value * 2^24) as int64
__device__ __forceinline__ long long h2fx(unsigned u) {
    unsigned hb = (u & 0x8000u) ? (u ^ 0x8000u) : (0xFFFFu & ~u);
    unsigned E = (hb >> 10) & 31, M = hb & 1023;
    long long mag = E ? ((long long)(1024 + M) << (E - 1)) : (long long)M;
    return (hb & 0x8000u) ? -mag : mag;
}

// =================== prep kernels ===========================================
__global__ void k_split_q(const float4* __restrict__ src) {
    size_t i = (size_t)blockIdx.x * 256 + threadIdx.x;
    float4 v = src[i];
    __half2* dh = (__half2*)g_qh;
    dh[2 * i]     = __floats2half2_rn(v.x * SCALE, v.y * SCALE);
    dh[2 * i + 1] = __floats2half2_rn(v.z * SCALE, v.w * SCALE);
}

__global__ void k_prep_k(const float* __restrict__ keys) {
    __shared__ float t[32][33];
    int b = blockIdx.z, d0 = blockIdx.x * 32, k0 = blockIdx.y * 32;
    int tx = threadIdx.x, ty = threadIdx.y;
#pragma unroll
    for (int j = 0; j < 4; j++) {
        int kk = k0 + ty + 8 * j;
        float f = keys[((size_t)b * LK + kk) * D_ + d0 + tx];
        t[ty + 8 * j][tx] = f;
        g_kh[((size_t)b * LK + kk) * D_ + d0 + tx] = __float2half_rn(f);
    }
    __syncthreads();
#pragma unroll
    for (int j = 0; j < 4; j++)
        g_kt[((size_t)b * D_ + d0 + ty + 8 * j) * LK + k0 + tx] =
            __float2half_rn(t[tx][ty + 8 * j]);
}

__global__ void k_prep_v(const float* __restrict__ v) {
    __shared__ float t[32][33];
    __shared__ float ps[8][33];
    int b = blockIdx.z, d0 = blockIdx.x * 32, kblk = blockIdx.y;
    int k0 = kblk * 32;
    int tx = threadIdx.x, ty = threadIdx.y;
#pragma unroll
    for (int j = 0; j < 4; j++)
        t[ty + 8 * j][tx] = v[((size_t)b * LK + k0 + ty + 8 * j) * D_ + d0 + tx];
    __syncthreads();
#pragma unroll
    for (int j = 0; j < 4; j++)
        g_vth[((size_t)b * D_ + d0 + ty + 8 * j) * LK + k0 + tx] =
            __float2half_rn(t[tx][ty + 8 * j]);
    float s = 0.f;
#pragma unroll
    for (int j = 0; j < 4; j++) s += t[ty * 4 + j][tx];
    ps[ty][tx] = s;
    __syncthreads();
    if (ty == 0) {
        double acc = 0.0;
#pragma unroll
        for (int j = 0; j < 8; j++) acc += (double)ps[j][tx];
        g_meanpart[((size_t)b * 128 + kblk) * D_ + d0 + tx] = acc;
    }
}

// ====== K_reduce: fp16 keys, 2-pass radix, merged pass2+sum (int64 exact) ===
__global__ void k_kreduce() {
    __shared__ unsigned short su[4096];
    __shared__ unsigned hist[256];
    __shared__ unsigned long long bsum[256];
    __shared__ unsigned long long redll[256];
    __shared__ unsigned s_pref, s_need;
    int bd = blockIdx.x;
    int tid = threadIdx.x;
    const __half2* kp = (const __half2*)(g_kt + (size_t)bd * LK);

    if (tid == 0) { s_pref = 0; s_need = LSEL; }
    hist[tid] = 0;
    __syncthreads();

    // load + convert + store su + pass-1 histogram (fused)
#pragma unroll
    for (int j = 0; j < 8; j++) {
        int i = tid + 256 * j;
        __half2 h2 = kp[i];
        unsigned bits = *(const unsigned*)&h2;
        unsigned u0 = h2sort(bits & 0xFFFFu);
        unsigned u1 = h2sort(bits >> 16);
        su[2 * i]     = (unsigned short)u0;
        su[2 * i + 1] = (unsigned short)u1;
        atomicAdd(&hist[u0 >> 8], 1);
        atomicAdd(&hist[u1 >> 8], 1);
    }
    __syncthreads();
    if (tid == 0) {
        unsigned cum = 0, need = LSEL;
        for (int bin = 255; bin >= 0; bin--) {
            unsigned c = hist[bin];
            if (cum + c >= need) { s_need = need - cum; s_pref = (unsigned)bin; break; }
            cum += c;
        }
    }
    __syncthreads();
    unsigned pref = s_pref;
    hist[tid] = 0;
    bsum[tid] = 0ULL;
    __syncthreads();
    // merged pass 2: low-byte hist + per-bin value sums (==pref), thread sums (>pref)
    long long mysum = 0;
    for (int i = tid; i < 4096; i += 256) {
        unsigned u = su[i];
        unsigned hi = u >> 8;
        if (hi >= pref) {
            long long fx = h2fx(u);
            if (hi > pref) mysum += fx;
            else {
                atomicAdd(&hist[u & 255], 1u);
                atomicAdd(&bsum[u & 255], (unsigned long long)fx);
            }
        }
    }
    redll[tid] = (unsigned long long)mysum;
    __syncthreads();
    for (int t = 128; t > 0; t >>= 1) {
        if (tid < t) redll[tid] += redll[tid + t];
        __syncthreads();
    }
    if (tid == 0) {
        unsigned cum = 0, need = s_need, lowbin = 0, nneed = 0;
        long long tot = (long long)redll[0];
        for (int bin = 255; bin >= 0; bin--) {
            unsigned c = hist[bin];
            if (cum + c >= need) { nneed = need - cum; lowbin = (unsigned)bin; break; }
            cum += c;
            tot += (long long)bsum[bin];
        }
        unsigned tu = (pref << 8) | lowbin;
        tot += (long long)nneed * h2fx(tu);
        g_kreduce[bd] = (float)(((double)tot / 16777216.0) / (double)LSEL);
    }
}

__global__ void k_meanfin() {
    int b = blockIdx.x, d = threadIdx.x;
    double s = 0.0;
    for (int j = 0; j < 128; j++) s += g_meanpart[((size_t)b * 128 + j) * D_ + d];
    g_meanvals[b * D_ + d] = (float)(s / (double)LK);
}

// =========== sqk = Q . K_reduce (compensated fp32, fp64-free inner) =========
__global__ void k_sqk(const float* __restrict__ queries) {
    __shared__ float kr[D_];
    int warp = threadIdx.x >> 5, lane = threadIdx.x & 31;
    int qflat = blockIdx.x * 8 + warp;
    int b = qflat >> 12;
    for (int i = threadIdx.x; i < D_; i += 256) kr[i] = g_kreduce[b * D_ + i];
    __syncthreads();
    const float* qp = queries + (size_t)qflat * D_;
    float s = 0.f, c = 0.f;
#pragma unroll
    for (int j = 0; j < 16; j++) {
        int d = lane + 32 * j;
        float a = qp[d], kk = kr[d];
        float p = __fmul_rn(a, kk);
        float e = __fmaf_rn(a, kk, -p);          // exact product tail
        float t = s + p;
        float z = (fabsf(s) >= fabsf(p)) ? ((s - t) + p) : ((p - t) + s);  // Neumaier
        s = t;
        c += z + e;
    }
    double acc = (double)s + (double)c;
    for (int off = 16; off; off >>= 1) acc += __shfl_down_sync(0xffffffffu, acc, off);
    if (lane == 0) g_sqk[qflat] = (float)acc;
}

// =================== threshold + compaction (fused, exact 32-bit radix) =====
__global__ void k_thresh() {
    __shared__ unsigned su[4096];
    __shared__ unsigned hist[256];
    __shared__ unsigned s_pref, s_need;
    int b = blockIdx.x, tid = threadIdx.x;
    if (tid == 0) { s_pref = 0; s_need = LSEL; g_selcnt[b] = 0; }
    __syncthreads();
    for (int i = tid; i < 4096; i += 256) su[i] = f2sort(g_sqk[b * LQ + i]);
    __syncthreads();
    unsigned pref = 0, need = LSEL;
    for (int pass = 3; pass >= 0; pass--) {
        hist[tid] = 0;
        __syncthreads();
        for (int i = tid; i < 4096; i += 256) {
            unsigned u = su[i];
            unsigned hi = (pass == 3) ? 0u : (u >> ((pass + 1) * 8));
            if (hi == pref) atomicAdd(&hist[(u >> (pass * 8)) & 255], 1);
        }
        __syncthreads();
        if (tid == 0) {
            unsigned cum = 0;
            for (int bin = 255; bin >= 0; bin--) {
                unsigned c = hist[bin];
                if (cum + c >= need) {
                    s_need = need - cum;
                    s_pref = (pref << 8) | (unsigned)bin;
                    break;
                }
                cum += c;
            }
        }
        __syncthreads();
        pref = s_pref; need = s_need;
        __syncthreads();
    }
    unsigned tu = s_pref;
    if (tid == 0) g_thresh[b] = sort2f(tu);
    for (int i = tid; i < 4096; i += 256) {
        if (su[i] >= tu) {
            int pos = atomicAdd(&g_selcnt[b], 1);
            if (pos < LSEL) g_selidx[b * LSEL + pos] = i;
        }
    }
}

__global__ void k_fill(float* __restrict__ out) {
    int r = blockIdx.x, b = r >> 12;
    if (g_sqk[r] < g_thresh[b]) {
        const float4* mv = (const float4*)(g_meanvals + b * D_);
        float4* op = (float4*)(out + (size_t)r * D_);
        op[threadIdx.x] = mv[threadIdx.x];
    }
}

// =================== 1-pass fp16 tile compute (128x128, warp 32x64) =========
__device__ __forceinline__ void gemm_stage1(uint32_t st, int wm, int wn, int lane,
                                            float d[2][8][4]) {
    int rA = wm * 32 + (lane & 15);
    int kA = (lane >> 4) * 16;
    int rB = wn * 64 + (lane & 7) + ((lane >> 4) << 3);
    int kB = ((lane >> 3) & 1) * 16;
#pragma unroll
    for (int t = 0; t < 4; t++) {
        uint32_t a0[4], a1[4];
        LDSM4(a0, swaddr(st, rA, t * 32 + kA));
        LDSM4(a1, swaddr(st, rA + 16, t * 32 + kA));
#pragma unroll
        for (int p = 0; p < 4; p++) {
            uint32_t bh[4];
            LDSM4(bh, swaddr(st + 16384, rB + p * 16, t * 32 + kB));
            MMAH(d[0][2 * p],     a0, bh[0], bh[1]);
            MMAH(d[0][2 * p + 1], a0, bh[2], bh[3]);
            MMAH(d[1][2 * p],     a1, bh[0], bh[1]);
            MMAH(d[1][2 * p + 1], a1, bh[2], bh[3]);
        }
    }
}

#define SMEM_DYN (3 * 32768)

// =================== GEMM 1: E = exp(Qsel@K^T), row-sum partials ============
__global__ void __launch_bounds__(256, 2) k_gemm_qk() {
    extern __shared__ char dsm[];
    __shared__ int srow[128];
    __shared__ float zsh[2][128];
    uint32_t sb = smem_u32(dsm);
    int tid = threadIdx.x;
    int b = blockIdx.z, m0 = blockIdx.y * 128, n0 = blockIdx.x * 128;

    if (tid < 128) {
        int m = m0 + tid;
        srow[tid] = g_selidx[b * LSEL + (m < LSEL ? m : 0)];
    }
    __syncthreads();

    const __half* baseA = g_qh + (size_t)b * LQ * D_;
    const __half* baseB = g_kh + ((size_t)b * LK + n0) * D_;

#define QK_FILL(s, k) do {                                                     \
    uint32_t st_ = sb + (s) * 32768;                                           \
    int k0_ = (k) * 64;                                                        \
    for (int idx = tid; idx < 2048; idx += 256) {                              \
        int tile_ = idx >> 10, r_ = (idx >> 3) & 127, seg_ = idx & 7;          \
        const __half* src_ = (tile_ == 0)                                      \
            ? baseA + (size_t)srow[r_] * D_ + k0_ + seg_ * 8                   \
            : baseB + (size_t)r_ * D_ + k0_ + seg_ * 8;                        \
        CP_ASYNC16(swaddr(st_ + tile_ * 16384, r_, seg_ * 16), src_);          \
    } CP_COMMIT(); } while (0)

    QK_FILL(0, 0); QK_FILL(1, 1); QK_FILL(2, 2);

    int lane = tid & 31, w = tid >> 5, wm = w >> 1, wn = w & 1;
    float d[2][8][4] = {};

    for (int k = 0; k < 8; k++) {
        int s = k % 3;
        if (k == 7) { CP_WAIT0(); } else { CP_WAIT2(); }
        __syncthreads();
        gemm_stage1(sb + s * 32768, wm, wn, lane, d);
        __syncthreads();
        if (k + 3 < 8) QK_FILL(s, k + 3);
    }

    float rs[2][2] = {};
#pragma unroll
    for (int i = 0; i < 2; i++)
#pragma unroll
        for (int j = 0; j < 8; j++) {
            d[i][j][0] = __expf(d[i][j][0]);
            d[i][j][1] = __expf(d[i][j][1]);
            d[i][j][2] = __expf(d[i][j][2]);
            d[i][j][3] = __expf(d[i][j][3]);
            rs[i][0] += d[i][j][0] + d[i][j][1];
            rs[i][1] += d[i][j][2] + d[i][j][3];
        }
#pragma unroll
    for (int i = 0; i < 2; i++)
#pragma unroll
        for (int h = 0; h < 2; h++) {
            rs[i][h] += __shfl_xor_sync(0xffffffffu, rs[i][h], 1);
            rs[i][h] += __shfl_xor_sync(0xffffffffu, rs[i][h], 2);
        }
    if ((lane & 3) == 0) {
        int rl = wm * 32 + (lane >> 2);
        zsh[wn][rl]      = rs[0][0];
        zsh[wn][rl + 8]  = rs[0][1];
        zsh[wn][rl + 16] = rs[1][0];
        zsh[wn][rl + 24] = rs[1][1];
    }

    int mBase = m0 + wm * 32, nBase = n0 + wn * 64;
#pragma unroll
    for (int i = 0; i < 2; i++) {
        int r = mBase + i * 16 + (lane >> 2);
#pragma unroll
        for (int j = 0; j < 8; j++) {
            int c = nBase + j * 8 + (lane & 3) * 2;
            if (r < LSEL)
                *(__half2*)(g_E + ((size_t)b * MPAD + r) * LK + c) =
                    __floats2half2_rn(d[i][j][0], d[i][j][1]);
            if (r + 8 < LSEL)
                *(__half2*)(g_E + ((size_t)b * MPAD + r + 8) * LK + c) =
                    __floats2half2_rn(d[i][j][2], d[i][j][3]);
        }
    }
    __syncthreads();
    if (tid < 128) {
        float z = zsh[0][tid] + zsh[1][tid];
        g_Zpart[(size_t)(b * MPAD + m0 + tid) * 32 + blockIdx.x] = z;
    }
}

// =================== GEMM 2: O = (E @ V)/Z, scatter, Z folded ===============
__global__ void __launch_bounds__(256, 2) k_gemm_pv(float* __restrict__ out) {
    extern __shared__ char dsm[];
    __shared__ int srow[128];
    __shared__ float zrow[128];
    uint32_t sb = smem_u32(dsm);
    int tid = threadIdx.x;
    int b = blockIdx.z, m0 = blockIdx.y * 128, n0 = blockIdx.x * 128;

    if (tid < 128) {
        int m = m0 + tid;
        srow[tid] = g_selidx[b * LSEL + (m < LSEL ? m : 0)];
    }
    __syncthreads();

    const __half* baseA = g_E + ((size_t)b * MPAD + m0) * LK;
    const __half* baseB = g_vth + ((size_t)b * D_ + n0) * LK;

#define PV_FILL(s, k) do {                                                     \
    uint32_t st_ = sb + (s) * 32768;                                           \
    int k0_ = (k) * 64;                                                        \
    for (int idx = tid; idx < 2048; idx += 256) {                              \
        int tile_ = idx >> 10, r_ = (idx >> 3) & 127, seg_ = idx & 7;          \
        const __half* src_ = (tile_ == 0)                                      \
            ? baseA + (size_t)r_ * LK + k0_ + seg_ * 8                         \
            : baseB + (size_t)r_ * LK + k0_ + seg_ * 8;                        \
        CP_ASYNC16(swaddr(st_ + tile_ * 16384, r_, seg_ * 16), src_);          \
    } CP_COMMIT(); } while (0)

    PV_FILL(0, 0); PV_FILL(1, 1); PV_FILL(2, 2);

    int lane = tid & 31, w = tid >> 5, wm = w >> 1, wn = w & 1;
    float d[2][8][4] = {};

    for (int k = 0; k < 64; k++) {
        int s = k % 3;
        if (k == 63) { CP_WAIT0(); } else { CP_WAIT2(); }
        __syncthreads();
        gemm_stage1(sb + s * 32768, wm, wn, lane, d);
        __syncthreads();
        if (k + 3 < 64) PV_FILL(s, k + 3);
    }

    if (tid < 128) {
        const float* p = g_Zpart + (size_t)(b * MPAD + m0 + tid) * 32;
        float s = 0.f;
#pragma unroll
        for (int i = 0; i < 32; i++) s += p[i];
        zrow[tid] = s;
    }
    __syncthreads();

    int nBase = n0 + wn * 64;
#pragma unroll
    for (int i = 0; i < 2; i++) {
        int lr = wm * 32 + i * 16 + (lane >> 2);
        int m = m0 + lr;
        float zi0 = 1.0f / zrow[lr];
        float zi1 = 1.0f / zrow[lr + 8];
        int q0 = srow[lr], q1 = srow[lr + 8];
#pragma unroll
        for (int j = 0; j < 8; j++) {
            int c = nBase + j * 8 + (lane & 3) * 2;
            if (m < LSEL)
                *(float2*)(out + ((size_t)b * LQ + q0) * D_ + c) =
                    float2{d[i][j][0] * zi0, d[i][j][1] * zi0};
            if (m + 8 < LSEL)
                *(float2*)(out + ((size_t)b * LQ + q1) * D_ + c) =
                    float2{d[i][j][2] * zi1, d[i][j][3] * zi1};
        }
    }
}

// =================== streams/events (created at static init, pre-capture) ==
static cudaStream_t hx_sb = nullptr;
static cudaEvent_t hx_ev0, hx_evQ, hx_evV, hx_evB, hx_evJ;
static void hx_init() {
    if (!hx_sb) {
        cudaStreamCreateWithFlags(&hx_sb, cudaStreamNonBlocking);
        cudaEventCreateWithFlags(&hx_ev0, cudaEventDisableTiming);
        cudaEventCreateWithFlags(&hx_evQ, cudaEventDisableTiming);
        cudaEventCreateWithFlags(&hx_evV, cudaEventDisableTiming);
        cudaEventCreateWithFlags(&hx_evB, cudaEventDisableTiming);
        cudaEventCreateWithFlags(&hx_evJ, cudaEventDisableTiming);
    }
}
static struct HxInit { HxInit() { hx_init(); } } hx_init_obj;

// =================== launch ==================================================
extern "C" void kernel_launch(void* const* d_in, const int* in_sizes, int n_in,
                              void* d_out, int out_size) {
    const float* q = (const float*)d_in[0];
    const float* k = (const float*)d_in[1];
    const float* v = (const float*)d_in[2];
    float* out = (float*)d_out;

    hx_init();
    cudaFuncSetAttribute(k_gemm_qk, cudaFuncAttributeMaxDynamicSharedMemorySize, SMEM_DYN);
    cudaFuncSetAttribute(k_gemm_pv, cudaFuncAttributeMaxDynamicSharedMemorySize, SMEM_DYN);

    // fork side stream
    cudaEventRecord(hx_ev0, 0);
    cudaStreamWaitEvent(hx_sb, hx_ev0, 0);

    // side: Q split, V prep, means — off the selection critical path
    k_split_q<<<16384, 256, 0, hx_sb>>>((const float4*)q);
    cudaEventRecord(hx_evQ, hx_sb);
    k_prep_v<<<dim3(16, 128, 8), dim3(32, 8), 0, hx_sb>>>(v);
    k_meanfin<<<B_, 512, 0, hx_sb>>>();
    cudaEventRecord(hx_evV, hx_sb);

    // main: selection critical path
    k_prep_k<<<dim3(16, 128, 8), dim3(32, 8)>>>(k);
    k_kreduce<<<B_ * D_, 256>>>();
    k_sqk<<<B_ * LQ / 8, 256>>>(q);
    k_thresh<<<B_, 256>>>();
    cudaEventRecord(hx_evB, 0);

    // side: fill unselected rows (needs thresh + meanvals); overlaps QK/PV
    cudaStreamWaitEvent(hx_sb, hx_evB, 0);
    k_fill<<<B_ * LQ, 128, 0, hx_sb>>>(out);
    cudaEventRecord(hx_evJ, hx_sb);

    // main: QK (needs split_q + selection)
    cudaStreamWaitEvent(0, hx_evQ, 0);
    dim3 g1(LK / 128, (LSEL + 127) / 128, B_);   // 32 x 22 x 8
    k_gemm_qk<<<g1, 256, SMEM_DYN>>>();

    // main: PV (needs E/Zpart + vth); fill writes disjoint rows of out
    cudaStreamWaitEvent(0, hx_evV, 0);
    dim3 g2(D_ / 128, (LSEL + 127) / 128, B_);   // 4 x 22 x 8
    k_gemm_pv<<<g2, 256, SMEM_DYN>>>(out);

    // join side stream before the graph's end
    cudaStreamWaitEvent(0, hx_evJ, 0);
}

// round 15
// speedup vs baseline: 1.0254x; 1.0254x over previous
#include <cuda_runtime.h>
#include <cuda_fp16.h>
#include <cstdint>

#define B_    8
#define LQ    4096
#define LK    4096
#define D_    512
#define LSEL  2744
#define MPAD  2816
#define SCALE 0.04419417382415922f   // 1/sqrt(512)

// ============================ device scratch ================================
__device__ __half g_qh[B_ * LQ * D_];           // Q*SCALE fp16
__device__ __half g_kh[B_ * LK * D_];           // K fp16
__device__ __half g_vth[B_ * D_ * LK];          // V^T fp16 [b][d][k]
__device__ __half g_E[(size_t)B_ * MPAD * LK];  // exp(S) fp16 [b][m][k]
__device__ __half g_kt[(size_t)B_ * D_ * LK];   // K^T fp16 [b][d][k]
__device__ float  g_Zpart[B_ * MPAD * 32];
__device__ float  g_kreduce[B_ * D_];
__device__ double g_meanpart[B_ * 128 * D_];
__device__ float  g_meanvals[B_ * D_];
__device__ float  g_sqk[B_ * LQ];
__device__ float  g_thresh[B_];
__device__ int    g_selidx[B_ * LSEL];
__device__ int    g_selcnt[B_];

// ============================ PTX helpers ===================================
__device__ __forceinline__ uint32_t smem_u32(const void* p) {
    uint32_t a;
    asm("{ .reg .u64 t; cvta.to.shared.u64 t, %1; cvt.u32.u64 %0, t; }" : "=r"(a) : "l"(p));
    return a;
}

#define CP_ASYNC16(dst, src) \
    asm volatile("cp.async.cg.shared.global [%0], [%1], 16;" :: "r"(dst), "l"(src) : "memory")
#define CP_COMMIT() asm volatile("cp.async.commit_group;" ::: "memory")
#define CP_WAIT2()  asm volatile("cp.async.wait_group 2;" ::: "memory")
#define CP_WAIT0()  asm volatile("cp.async.wait_group 0;" ::: "memory")

#define LDSM4(r, a) \
    asm volatile("ldmatrix.sync.aligned.m8n8.x4.shared.b16 {%0,%1,%2,%3}, [%4];" \
        : "=r"((r)[0]), "=r"((r)[1]), "=r"((r)[2]), "=r"((r)[3]) : "r"(a))

#define MMAH(d, a, b0, b1) \
    asm volatile("mma.sync.aligned.m16n8k16.row.col.f32.f16.f16.f32 " \
        "{%0,%1,%2,%3}, {%4,%5,%6,%7}, {%8,%9}, {%0,%1,%2,%3};" \
        : "+f"((d)[0]), "+f"((d)[1]), "+f"((d)[2]), "+f"((d)[3]) \
        : "r"((a)[0]), "r"((a)[1]), "r"((a)[2]), "r"((a)[3]), "r"(b0), "r"(b1))

// swizzled addr inside one tile of 128-byte rows (SW128)
__device__ __forceinline__ uint32_t swaddr(uint32_t base, int row, int kb) {
    uint32_t o = (uint32_t)(row * 128 + kb);
    return base + (o ^ ((o >> 3) & 0x70));
}

__device__ __forceinline__ unsigned f2sort(float f) {
    unsigned u = __float_as_uint(f);
    return (u & 0x80000000u) ? ~u : (u | 0x80000000u);
}
__device__ __forceinline__ float sort2f(unsigned u) {
    unsigned fb = (u & 0x80000000u) ? (u ^ 0x80000000u) : ~u;
    return __uint_as_float(fb);
}
__device__ __forceinline__ unsigned h2sort(unsigned hbits) {
    return (hbits & 0x8000u) ? (0xFFFFu & ~hbits) : (hbits | 0x8000u);
}
__device__ __forceinline__ float sort2h(unsigned u) {
    unsigned hb = (u & 0x8000u) ? (u ^ 0x8000u) : (0xFFFFu & ~u);
    __half h = __ushort_as_half((unsigned short)hb);
    return __half2float(h);
}

// =================== prep kernels ===========================================
__global__ void k_split_q(const float4* __restrict__ src) {
    size_t i = (size_t)blockIdx.x * 256 + threadIdx.x;
    float4 v = src[i];
    __half2* dh = (__half2*)g_qh;
    dh[2 * i]     = __floats2half2_rn(v.x * SCALE, v.y * SCALE);
    dh[2 * i + 1] = __floats2half2_rn(v.z * SCALE, v.w * SCALE);
}

// side: K -> fp16 row-major (streaming, no transpose)
__global__ void k_prep_kh(const float4* __restrict__ src) {
    size_t i = (size_t)blockIdx.x * 256 + threadIdx.x;
    float4 v = src[i];
    __half2* dh = (__half2*)g_kh;
    dh[2 * i]     = __floats2half2_rn(v.x, v.y);
    dh[2 * i + 1] = __floats2half2_rn(v.z, v.w);
}

// critical: K -> fp16 K^T only
__global__ void k_prep_kt(const float* __restrict__ keys) {
    __shared__ float t[32][33];
    int b = blockIdx.z, d0 = blockIdx.x * 32, k0 = blockIdx.y * 32;
    int tx = threadIdx.x, ty = threadIdx.y;
#pragma unroll
    for (int j = 0; j < 4; j++)
        t[ty + 8 * j][tx] = keys[((size_t)b * LK + k0 + ty + 8 * j) * D_ + d0 + tx];
    __syncthreads();
#pragma unroll
    for (int j = 0; j < 4; j++)
        g_kt[((size_t)b * D_ + d0 + ty + 8 * j) * LK + k0 + tx] =
            __float2half_rn(t[tx][ty + 8 * j]);
}

__global__ void k_prep_v(const float* __restrict__ v) {
    __shared__ float t[32][33];
    __shared__ float ps[8][33];
    int b = blockIdx.z, d0 = blockIdx.x * 32, kblk = blockIdx.y;
    int k0 = kblk * 32;
    int tx = threadIdx.x, ty = threadIdx.y;
#pragma unroll
    for (int j = 0; j < 4; j++)
        t[ty + 8 * j][tx] = v[((size_t)b * LK + k0 + ty + 8 * j) * D_ + d0 + tx];
    __syncthreads();
#pragma unroll
    for (int j = 0; j < 4; j++)
        g_vth[((size_t)b * D_ + d0 + ty + 8 * j) * LK + k0 + tx] =
            __float2half_rn(t[tx][ty + 8 * j]);
    float s = 0.f;
#pragma unroll
    for (int j = 0; j < 4; j++) s += t[ty * 4 + j][tx];
    ps[ty][tx] = s;
    __syncthreads();
    if (ty == 0) {
        double acc = 0.0;
#pragma unroll
        for (int j = 0; j < 8; j++) acc += (double)ps[j][tx];
        g_meanpart[((size_t)b * 128 + kblk) * D_ + d0 + tx] = acc;
    }
}

// =================== K_reduce: fp16 keys, 2-pass radix (R11/R13 version) ====
__global__ void k_kreduce() {
    __shared__ unsigned short su[4096];
    __shared__ unsigned hist[256];
    __shared__ unsigned s_pref, s_need;
    __shared__ double red[256];
    int bd = blockIdx.x;
    int tid = threadIdx.x;
    const __half2* kp = (const __half2*)(g_kt + (size_t)bd * LK);

    if (tid == 0) { s_pref = 0; s_need = LSEL; }
    hist[tid] = 0;
    __syncthreads();

#pragma unroll
    for (int j = 0; j < 8; j++) {
        int i = tid + 256 * j;
        __half2 h2 = kp[i];
        unsigned bits = *(const unsigned*)&h2;
        unsigned u0 = h2sort(bits & 0xFFFFu);
        unsigned u1 = h2sort(bits >> 16);
        su[2 * i]     = (unsigned short)u0;
        su[2 * i + 1] = (unsigned short)u1;
        atomicAdd(&hist[u0 >> 8], 1);
        atomicAdd(&hist[u1 >> 8], 1);
    }
    __syncthreads();
    if (tid == 0) {
        unsigned cum = 0, need = LSEL;
        for (int bin = 255; bin >= 0; bin--) {
            unsigned c = hist[bin];
            if (cum + c >= need) { s_need = need - cum; s_pref = (unsigned)bin; break; }
            cum += c;
        }
    }
    __syncthreads();
    unsigned pref = s_pref;
    hist[tid] = 0;
    __syncthreads();
    for (int i = tid; i < 4096; i += 256) {
        unsigned u = su[i];
        if ((u >> 8) == pref) atomicAdd(&hist[u & 255], 1);
    }
    __syncthreads();
    if (tid == 0) {
        unsigned cum = 0, need = s_need;
        for (int bin = 255; bin >= 0; bin--) {
            unsigned c = hist[bin];
            if (cum + c >= need) { s_need = need - cum; s_pref = (pref << 8) | (unsigned)bin; break; }
            cum += c;
        }
    }
    __syncthreads();
    unsigned tu = s_pref, need = s_need;
    double acc = 0.0;
    for (int i = tid; i < 4096; i += 256) {
        unsigned u = su[i];
        if (u > tu) acc += (double)sort2h(u);
    }
    red[tid] = acc;
    __syncthreads();
    for (int t = 128; t > 0; t >>= 1) {
        if (tid < t) red[tid] += red[tid + t];
        __syncthreads();
    }
    if (tid == 0)
        g_kreduce[bd] = (float)((red[0] + (double)need * (double)sort2h(tu)) / (double)LSEL);
}

__global__ void k_meanfin() {
    int b = blockIdx.x, d = threadIdx.x;
    double s = 0.0;
    for (int j = 0; j < 128; j++) s += g_meanpart[((size_t)b * 128 + j) * D_ + d];
    g_meanvals[b * D_ + d] = (float)(s / (double)LK);
}

// =================== sqk = Q . K_reduce (fp64, R13 version) ==================
__global__ void k_sqk(const float* __restrict__ queries) {
    __shared__ float kr[D_];
    int warp = threadIdx.x >> 5, lane = threadIdx.x & 31;
    int qflat = blockIdx.x * 8 + warp;
    int b = qflat >> 12;
    for (int i = threadIdx.x; i < D_; i += 256) kr[i] = g_kreduce[b * D_ + i];
    __syncthreads();
    const float* qp = queries + (size_t)qflat * D_;
    double acc = 0.0;
#pragma unroll
    for (int j = 0; j < 16; j++) {
        int d = lane + 32 * j;
        acc += (double)qp[d] * (double)kr[d];
    }
    for (int off = 16; off; off >>= 1) acc += __shfl_down_sync(0xffffffffu, acc, off);
    if (lane == 0) g_sqk[qflat] = (float)acc;
}

// ============ threshold + compaction (fused, exact 32-bit radix, 1024t) =====
__global__ void k_thresh() {
    __shared__ unsigned su[4096];
    __shared__ unsigned hist[256];
    __shared__ unsigned s_pref, s_need;
    int b = blockIdx.x, tid = threadIdx.x;
    if (tid == 0) { s_pref = 0; s_need = LSEL; g_selcnt[b] = 0; }
    __syncthreads();
    for (int i = tid; i < 4096; i += 1024) su[i] = f2sort(g_sqk[b * LQ + i]);
    __syncthreads();
    unsigned pref = 0, need = LSEL;
    for (int pass = 3; pass >= 0; pass--) {
        if (tid < 256) hist[tid] = 0;
        __syncthreads();
        for (int i = tid; i < 4096; i += 1024) {
            unsigned u = su[i];
            unsigned hi = (pass == 3) ? 0u : (u >> ((pass + 1) * 8));
            if (hi == pref) atomicAdd(&hist[(u >> (pass * 8)) & 255], 1);
        }
        __syncthreads();
        if (tid == 0) {
            unsigned cum = 0;
            for (int bin = 255; bin >= 0; bin--) {
                unsigned c = hist[bin];
                if (cum + c >= need) {
                    s_need = need - cum;
                    s_pref = (pref << 8) | (unsigned)bin;
                    break;
                }
                cum += c;
            }
        }
        __syncthreads();
        pref = s_pref; need = s_need;
        __syncthreads();
    }
    unsigned tu = s_pref;
    if (tid == 0) g_thresh[b] = sort2f(tu);
    for (int i = tid; i < 4096; i += 1024) {
        if (su[i] >= tu) {
            int pos = atomicAdd(&g_selcnt[b], 1);
            if (pos < LSEL) g_selidx[b * LSEL + pos] = i;
        }
    }
}

__global__ void k_fill(float* __restrict__ out) {
    int r = blockIdx.x, b = r >> 12;
    if (g_sqk[r] < g_thresh[b]) {
        const float4* mv = (const float4*)(g_meanvals + b * D_);
        float4* op = (float4*)(out + (size_t)r * D_);
        op[threadIdx.x] = mv[threadIdx.x];
    }
}

// =================== 1-pass fp16 tile compute (128x128, warp 32x64) =========
__device__ __forceinline__ void gemm_stage1(uint32_t st, int wm, int wn, int lane,
                                            float d[2][8][4]) {
    int rA = wm * 32 + (lane & 15);
    int kA = (lane >> 4) * 16;
    int rB = wn * 64 + (lane & 7) + ((lane >> 4) << 3);
    int kB = ((lane >> 3) & 1) * 16;
#pragma unroll
    for (int t = 0; t < 4; t++) {
        uint32_t a0[4], a1[4];
        LDSM4(a0, swaddr(st, rA, t * 32 + kA));
        LDSM4(a1, swaddr(st, rA + 16, t * 32 + kA));
#pragma unroll
        for (int p = 0; p < 4; p++) {
            uint32_t bh[4];
            LDSM4(bh, swaddr(st + 16384, rB + p * 16, t * 32 + kB));
            MMAH(d[0][2 * p],     a0, bh[0], bh[1]);
            MMAH(d[0][2 * p + 1], a0, bh[2], bh[3]);
            MMAH(d[1][2 * p],     a1, bh[0], bh[1]);
            MMAH(d[1][2 * p + 1], a1, bh[2], bh[3]);
        }
    }
}

#define SMEM_DYN (3 * 32768)

// =================== GEMM 1: E = exp(Qsel@K^T), row-sum partials ============
__global__ void __launch_bounds__(256, 2) k_gemm_qk() {
    extern __shared__ char dsm[];
    __shared__ int srow[128];
    __shared__ float zsh[2][128];
    uint32_t sb = smem_u32(dsm);
    int tid = threadIdx.x;
    int b = blockIdx.z, m0 = blockIdx.y * 128, n0 = blockIdx.x * 128;

    if (tid < 128) {
        int m = m0 + tid;
        srow[tid] = g_selidx[b * LSEL + (m < LSEL ? m : 0)];
    }
    __syncthreads();

    const __half* baseA = g_qh + (size_t)b * LQ * D_;
    const __half* baseB = g_kh + ((size_t)b * LK + n0) * D_;

#define QK_FILL(s, k) do {                                                     \
    uint32_t st_ = sb + (s) * 32768;                                           \
    int k0_ = (k) * 64;                                                        \
    for (int idx = tid; idx < 2048; idx += 256) {                              \
        int tile_ = idx >> 10, r_ = (idx >> 3) & 127, seg_ = idx & 7;          \
        const __half* src_ = (tile_ == 0)                                      \
            ? baseA + (size_t)srow[r_] * D_ + k0_ + seg_ * 8                   \
            : baseB + (size_t)r_ * D_ + k0_ + seg_ * 8;                        \
        CP_ASYNC16(swaddr(st_ + tile_ * 16384, r_, seg_ * 16), src_);          \
    } CP_COMMIT(); } while (0)

    QK_FILL(0, 0); QK_FILL(1, 1); QK_FILL(2, 2);

    int lane = tid & 31, w = tid >> 5, wm = w >> 1, wn = w & 1;
    float d[2][8][4] = {};

    for (int k = 0; k < 8; k++) {
        int s = k % 3;
        if (k == 7) { CP_WAIT0(); } else { CP_WAIT2(); }
        __syncthreads();
        gemm_stage1(sb + s * 32768, wm, wn, lane, d);
        __syncthreads();
        if (k + 3 < 8) QK_FILL(s, k + 3);
    }

    float rs[2][2] = {};
#pragma unroll
    for (int i = 0; i < 2; i++)
#pragma unroll
        for (int j = 0; j < 8; j++) {
            d[i][j][0] = __expf(d[i][j][0]);
            d[i][j][1] = __expf(d[i][j][1]);
            d[i][j][2] = __expf(d[i][j][2]);
            d[i][j][3] = __expf(d[i][j][3]);
            rs[i][0] += d[i][j][0] + d[i][j][1];
            rs[i][1] += d[i][j][2] + d[i][j][3];
        }
#pragma unroll
    for (int i = 0; i < 2; i++)
#pragma unroll
        for (int h = 0; h < 2; h++) {
            rs[i][h] += __shfl_xor_sync(0xffffffffu, rs[i][h], 1);
            rs[i][h] += __shfl_xor_sync(0xffffffffu, rs[i][h], 2);
        }
    if ((lane & 3) == 0) {
        int rl = wm * 32 + (lane >> 2);
        zsh[wn][rl]      = rs[0][0];
        zsh[wn][rl + 8]  = rs[0][1];
        zsh[wn][rl + 16] = rs[1][0];
        zsh[wn][rl + 24] = rs[1][1];
    }

    int mBase = m0 + wm * 32, nBase = n0 + wn * 64;
#pragma unroll
    for (int i = 0; i < 2; i++) {
        int r = mBase + i * 16 + (lane >> 2);
#pragma unroll
        for (int j = 0; j < 8; j++) {
            int c = nBase + j * 8 + (lane & 3) * 2;
            if (r < LSEL)
                *(__half2*)(g_E + ((size_t)b * MPAD + r) * LK + c) =
                    __floats2half2_rn(d[i][j][0], d[i][j][1]);
            if (r + 8 < LSEL)
                *(__half2*)(g_E + ((size_t)b * MPAD + r + 8) * LK + c) =
                    __floats2half2_rn(d[i][j][2], d[i][j][3]);
        }
    }
    __syncthreads();
    if (tid < 128) {
        float z = zsh[0][tid] + zsh[1][tid];
        g_Zpart[(size_t)(b * MPAD + m0 + tid) * 32 + blockIdx.x] = z;
    }
}

// =================== GEMM 2: O = (E @ V)/Z, scatter, Z folded ===============
__global__ void __launch_bounds__(256, 2) k_gemm_pv(float* __restrict__ out) {
    extern __shared__ char dsm[];
    __shared__ int srow[128];
    __shared__ float zrow[128];
    uint32_t sb = smem_u32(dsm);
    int tid = threadIdx.x;
    int b = blockIdx.z, m0 = blockIdx.y * 128, n0 = blockIdx.x * 128;

    if (tid < 128) {
        int m = m0 + tid;
        srow[tid] = g_selidx[b * LSEL + (m < LSEL ? m : 0)];
    }
    __syncthreads();

    const __half* baseA = g_E + ((size_t)b * MPAD + m0) * LK;
    const __half* baseB = g_vth + ((size_t)b * D_ + n0) * LK;

#define PV_FILL(s, k) do {                                                     \
    uint32_t st_ = sb + (s) * 32768;                                           \
    int k0_ = (k) * 64;                                                        \
    for (int idx = tid; idx < 2048; idx += 256) {                              \
        int tile_ = idx >> 10, r_ = (idx >> 3) & 127, seg_ = idx & 7;          \
        const __half* src_ = (tile_ == 0)                                      \
            ? baseA + (size_t)r_ * LK + k0_ + seg_ * 8                         \
            : baseB + (size_t)r_ * LK + k0_ + seg_ * 8;                        \
        CP_ASYNC16(swaddr(st_ + tile_ * 16384, r_, seg_ * 16), src_);          \
    } CP_COMMIT(); } while (0)

    PV_FILL(0, 0); PV_FILL(1, 1); PV_FILL(2, 2);

    int lane = tid & 31, w = tid >> 5, wm = w >> 1, wn = w & 1;
    float d[2][8][4] = {};

    for (int k = 0; k < 64; k++) {
        int s = k % 3;
        if (k == 63) { CP_WAIT0(); } else { CP_WAIT2(); }
        __syncthreads();
        gemm_stage1(sb + s * 32768, wm, wn, lane, d);
        __syncthreads();
        if (k + 3 < 64) PV_FILL(s, k + 3);
    }

    if (tid < 128) {
        const float* p = g_Zpart + (size_t)(b * MPAD + m0 + tid) * 32;
        float s = 0.f;
#pragma unroll
        for (int i = 0; i < 32; i++) s += p[i];
        zrow[tid] = s;
    }
    __syncthreads();

    int nBase = n0 + wn * 64;
#pragma unroll
    for (int i = 0; i < 2; i++) {
        int lr = wm * 32 + i * 16 + (lane >> 2);
        int m = m0 + lr;
        float zi0 = 1.0f / zrow[lr];
        float zi1 = 1.0f / zrow[lr + 8];
        int q0 = srow[lr], q1 = srow[lr + 8];
#pragma unroll
        for (int j = 0; j < 8; j++) {
            int c = nBase + j * 8 + (lane & 3) * 2;
            if (m < LSEL)
                *(float2*)(out + ((size_t)b * LQ + q0) * D_ + c) =
                    float2{d[i][j][0] * zi0, d[i][j][1] * zi0};
            if (m + 8 < LSEL)
                *(float2*)(out + ((size_t)b * LQ + q1) * D_ + c) =
                    float2{d[i][j][2] * zi1, d[i][j][3] * zi1};
        }
    }
}

// =================== streams/events (created at static init, pre-capture) ==
static cudaStream_t hx_sb = nullptr;
static cudaEvent_t hx_ev0, hx_evQ, hx_evV, hx_evB, hx_evJ;
static void hx_init() {
    if (!hx_sb) {
        cudaStreamCreateWithFlags(&hx_sb, cudaStreamNonBlocking);
        cudaEventCreateWithFlags(&hx_ev0, cudaEventDisableTiming);
        cudaEventCreateWithFlags(&hx_evQ, cudaEventDisableTiming);
        cudaEventCreateWithFlags(&hx_evV, cudaEventDisableTiming);
        cudaEventCreateWithFlags(&hx_evB, cudaEventDisableTiming);
        cudaEventCreateWithFlags(&hx_evJ, cudaEventDisableTiming);
    }
}
static struct HxInit { HxInit() { hx_init(); } } hx_init_obj;

// =================== launch ==================================================
extern "C" void kernel_launch(void* const* d_in, const int* in_sizes, int n_in,
                              void* d_out, int out_size) {
    const float* q = (const float*)d_in[0];
    const float* k = (const float*)d_in[1];
    const float* v = (const float*)d_in[2];
    float* out = (float*)d_out;

    hx_init();
    cudaFuncSetAttribute(k_gemm_qk, cudaFuncAttributeMaxDynamicSharedMemorySize, SMEM_DYN);
    cudaFuncSetAttribute(k_gemm_pv, cudaFuncAttributeMaxDynamicSharedMemorySize, SMEM_DYN);

    // fork side stream
    cudaEventRecord(hx_ev0, 0);
    cudaStreamWaitEvent(hx_sb, hx_ev0, 0);

    // side: K fp16, Q split, V prep, means — off the selection critical path
    k_prep_kh<<<16384, 256, 0, hx_sb>>>((const float4*)k);
    k_split_q<<<16384, 256, 0, hx_sb>>>((const float4*)q);
    cudaEventRecord(hx_evQ, hx_sb);
    k_prep_v<<<dim3(16, 128, 8), dim3(32, 8), 0, hx_sb>>>(v);
    k_meanfin<<<B_, 512, 0, hx_sb>>>();
    cudaEventRecord(hx_evV, hx_sb);

    // main: selection critical path
    k_prep_kt<<<dim3(16, 128, 8), dim3(32, 8)>>>(k);
    k_kreduce<<<B_ * D_, 256>>>();
    k_sqk<<<B_ * LQ / 8, 256>>>(q);
    k_thresh<<<B_, 1024>>>();
    cudaEventRecord(hx_evB, 0);

    // side: fill unselected rows (needs thresh + meanvals); overlaps QK/PV
    cudaStreamWaitEvent(hx_sb, hx_evB, 0);
    k_fill<<<B_ * LQ, 128, 0, hx_sb>>>(out);
    cudaEventRecord(hx_evJ, hx_sb);

    // main: QK (needs g_qh + g_kh + selection)
    cudaStreamWaitEvent(0, hx_evQ, 0);
    dim3 g1(LK / 128, (LSEL + 127) / 128, B_);   // 32 x 22 x 8
    k_gemm_qk<<<g1, 256, SMEM_DYN>>>();

    // main: PV (needs E/Zpart + vth); fill writes disjoint rows of out
    cudaStreamWaitEvent(0, hx_evV, 0);
    dim3 g2(D_ / 128, (LSEL + 127) / 128, B_);   // 4 x 22 x 8
    k_gemm_pv<<<g2, 256, SMEM_DYN>>>(out);

    // join side stream before the graph's end
    cudaStreamWaitEvent(0, hx_evJ, 0);
}

// round 16
// speedup vs baseline: 1.2219x; 1.1916x over previous
#include <cuda_runtime.h>
#include <cuda_fp16.h>
#include <cstdint>

#define B_    8
#define LQ    4096
#define LK    4096
#define D_    512
#define LSEL  2744
#define MPAD  2816
#define MT    22      // m tiles of 128
#define SCALE 0.04419417382415922f   // 1/sqrt(512)

// ==================== device scratch (tile-swizzled operands) ===============
// tile = 128 rows x 128 bytes (64 halfs), SW128-swizzled, 16 KB
__device__ __half g_qsel_t[(size_t)B_ * MT * 8 * 8192];   // Q*SCALE gathered [b][mt][kc]
__device__ __half g_kh_t[(size_t)B_ * 32 * 8 * 8192];     // K [b][nt][kc]
__device__ __half g_E_t[(size_t)B_ * MT * 64 * 8192];     // exp(S) [b][mt][kc]
__device__ __half g_vt_t[(size_t)B_ * 4 * 64 * 8192];     // V^T [b][nt][kc]
__device__ __half g_kt[(size_t)B_ * D_ * LK];             // K^T fp16 (kreduce)
__device__ float  g_Zpart[B_ * MPAD * 32];
__device__ float  g_kreduce[B_ * D_];
__device__ double g_meanpart[B_ * 128 * D_];
__device__ float  g_meanvals[B_ * D_];
__device__ float  g_sqk[B_ * LQ];
__device__ float  g_thresh[B_];
__device__ int    g_selidx[B_ * LSEL];
__device__ int    g_selcnt[B_];

// ============================ PTX helpers ===================================
__device__ __forceinline__ uint32_t smem_u32(const void* p) {
    uint32_t a;
    asm("{ .reg .u64 t; cvta.to.shared.u64 t, %1; cvt.u32.u64 %0, t; }" : "=r"(a) : "l"(p));
    return a;
}

#define MBAR_INIT(a, n) \
    asm volatile("mbarrier.init.shared.b64 [%0], %1;" :: "r"(a), "r"(n) : "memory")
#define MBAR_EXPECT(a, tx) \
    asm volatile("mbarrier.arrive.expect_tx.shared.b64 _, [%0], %1;" :: "r"(a), "r"(tx) : "memory")
#define MBAR_WAIT(a, ph) do {                                                  \
    unsigned _d = 0;                                                           \
    while (!_d) {                                                              \
        asm volatile("{\n\t.reg .pred P;\n\t"                                  \
            "mbarrier.try_wait.parity.shared.b64 P, [%1], %2;\n\t"             \
            "selp.b32 %0, 1, 0, P;\n\t}"                                       \
            : "=r"(_d) : "r"(a), "r"(ph) : "memory");                          \
    } } while (0)

#define BULK16K(dst, src, mbar) \
    asm volatile("cp.async.bulk.shared::cluster.global.mbarrier::complete_tx::bytes " \
        "[%0], [%1], %2, [%3];" \
        :: "r"(dst), "l"(src), "r"(16384), "r"(mbar) : "memory")

#define LDSM4(r, a) \
    asm volatile("ldmatrix.sync.aligned.m8n8.x4.shared.b16 {%0,%1,%2,%3}, [%4];" \
        : "=r"((r)[0]), "=r"((r)[1]), "=r"((r)[2]), "=r"((r)[3]) : "r"(a))

#define MMAH(d, a, b0, b1) \
    asm volatile("mma.sync.aligned.m16n8k16.row.col.f32.f16.f16.f32 " \
        "{%0,%1,%2,%3}, {%4,%5,%6,%7}, {%8,%9}, {%0,%1,%2,%3};" \
        : "+f"((d)[0]), "+f"((d)[1]), "+f"((d)[2]), "+f"((d)[3]) \
        : "r"((a)[0]), "r"((a)[1]), "r"((a)[2]), "r"((a)[3]), "r"(b0), "r"(b1))

__device__ __forceinline__ uint32_t swaddr(uint32_t base, int row, int kb) {
    uint32_t o = (uint32_t)(row * 128 + kb);
    return base + (o ^ ((o >> 3) & 0x70));
}
__device__ __forceinline__ uint32_t swz(uint32_t o) { return o ^ ((o >> 3) & 0x70); }

__device__ __forceinline__ unsigned f2sort(float f) {
    unsigned u = __float_as_uint(f);
    return (u & 0x80000000u) ? ~u : (u | 0x80000000u);
}
__device__ __forceinline__ float sort2f(unsigned u) {
    unsigned fb = (u & 0x80000000u) ? (u ^ 0x80000000u) : ~u;
    return __uint_as_float(fb);
}
__device__ __forceinline__ unsigned h2sort(unsigned hbits) {
    return (hbits & 0x8000u) ? (0xFFFFu & ~hbits) : (hbits | 0x8000u);
}
__device__ __forceinline__ float sort2h(unsigned u) {
    unsigned hb = (u & 0x8000u) ? (u ^ 0x8000u) : (0xFFFFu & ~u);
    __half h = __ushort_as_half((unsigned short)hb);
    return __half2float(h);
}

// =================== prep kernels ===========================================
// K -> fp16, tile-swizzled [b][nt(32)][kc(8)]
__global__ void k_prep_kh(const float4* __restrict__ keys) {
    size_t idx = (size_t)blockIdx.x * 256 + threadIdx.x;   // 2,097,152 total
    int seg = (int)(idx & 63);
    size_t row = idx >> 6;
    int b = (int)(row >> 12);
    int krow = (int)(row & 4095);
    const float4* src = keys + row * 128 + seg * 2;
    float4 v0 = src[0], v1 = src[1];
    int nt = krow >> 7, rloc = krow & 127, kc = seg >> 3, si = seg & 7;
    char* tb = (char*)g_kh_t + ((((size_t)b * 32 + nt) * 8 + kc) << 14);
    uint32_t o = swz((uint32_t)(rloc * 128 + si * 16));
    __half2 h[4] = { __floats2half2_rn(v0.x, v0.y), __floats2half2_rn(v0.z, v0.w),
                     __floats2half2_rn(v1.x, v1.y), __floats2half2_rn(v1.z, v1.w) };
    *(float4*)(tb + o) = *(float4*)h;
}

// K -> fp16 K^T (kreduce input)
__global__ void k_prep_kt(const float* __restrict__ keys) {
    __shared__ float t[32][33];
    int b = blockIdx.z, d0 = blockIdx.x * 32, k0 = blockIdx.y * 32;
    int tx = threadIdx.x, ty = threadIdx.y;
#pragma unroll
    for (int j = 0; j < 4; j++)
        t[ty + 8 * j][tx] = keys[((size_t)b * LK + k0 + ty + 8 * j) * D_ + d0 + tx];
    __syncthreads();
#pragma unroll
    for (int j = 0; j < 4; j++)
        g_kt[((size_t)b * D_ + d0 + ty + 8 * j) * LK + k0 + tx] =
            __float2half_rn(t[tx][ty + 8 * j]);
}

// V -> fp16 V^T tile-swizzled [b][nt(4)][kc(64)] + fp64 mean partials
__global__ void k_prep_v(const float* __restrict__ v) {
    __shared__ float t[32][33];
    __shared__ float ps[8][33];
    int b = blockIdx.z, d0 = blockIdx.x * 32, kblk = blockIdx.y;
    int k0 = kblk * 32;
    int tx = threadIdx.x, ty = threadIdx.y;
#pragma unroll
    for (int j = 0; j < 4; j++)
        t[ty + 8 * j][tx] = v[((size_t)b * LK + k0 + ty + 8 * j) * D_ + d0 + tx];
    __syncthreads();
#pragma unroll
    for (int j = 0; j < 4; j++) {
        int drow = d0 + ty + 8 * j;
        int kk = k0 + tx;
        char* tb = (char*)g_vt_t + ((((size_t)b * 4 + (drow >> 7)) * 64 + (kk >> 6)) << 14);
        uint32_t o = swz((uint32_t)((drow & 127) * 128 + (kk & 63) * 2));
        *(__half*)(tb + o) = __float2half_rn(t[tx][ty + 8 * j]);
    }
    float s = 0.f;
#pragma unroll
    for (int j = 0; j < 4; j++) s += t[ty * 4 + j][tx];
    ps[ty][tx] = s;
    __syncthreads();
    if (ty == 0) {
        double acc = 0.0;
#pragma unroll
        for (int j = 0; j < 8; j++) acc += (double)ps[j][tx];
        g_meanpart[((size_t)b * 128 + kblk) * D_ + d0 + tx] = acc;
    }
}

// gather selected Q rows -> scaled fp16, tile-swizzled [b][mt(22)][kc(8)]
__global__ void k_gather_q(const float4* __restrict__ q) {
    int blk = blockIdx.x;                 // b*MPAD + m
    int b = blk / MPAD, m = blk - b * MPAD;
    int tid = threadIdx.x;                // 128
    int e = tid * 4;
    int kc = e >> 6;
    char* tb = (char*)g_qsel_t + ((((size_t)b * MT + (m >> 7)) * 8 + kc) << 14);
    uint32_t o = swz((uint32_t)((m & 127) * 128 + (e & 63) * 2));
    __half2 h0, h1;
    if (m < LSEL) {
        int qi = g_selidx[b * LSEL + m];
        float4 v = q[((size_t)b * LQ + qi) * (D_ / 4) + tid];
        h0 = __floats2half2_rn(v.x * SCALE, v.y * SCALE);
        h1 = __floats2half2_rn(v.z * SCALE, v.w * SCALE);
    } else {
        h0 = __half2{__half(0.f), __half(0.f)};
        h1 = h0;
    }
    *(__half2*)(tb + o) = h0;
    *(__half2*)(tb + o + 4) = h1;
}

// =================== K_reduce: fp16 keys, 2-pass radix ======================
__global__ void k_kreduce() {
    __shared__ unsigned short su[4096];
    __shared__ unsigned hist[256];
    __shared__ unsigned s_pref, s_need;
    __shared__ double red[256];
    int bd = blockIdx.x;
    int tid = threadIdx.x;
    const __half2* kp = (const __half2*)(g_kt + (size_t)bd * LK);

    if (tid == 0) { s_pref = 0; s_need = LSEL; }
    hist[tid] = 0;
    __syncthreads();
#pragma unroll
    for (int j = 0; j < 8; j++) {
        int i = tid + 256 * j;
        __half2 h2 = kp[i];
        unsigned bits = *(const unsigned*)&h2;
        unsigned u0 = h2sort(bits & 0xFFFFu);
        unsigned u1 = h2sort(bits >> 16);
        su[2 * i]     = (unsigned short)u0;
        su[2 * i + 1] = (unsigned short)u1;
        atomicAdd(&hist[u0 >> 8], 1);
        atomicAdd(&hist[u1 >> 8], 1);
    }
    __syncthreads();
    if (tid == 0) {
        unsigned cum = 0, need = LSEL;
        for (int bin = 255; bin >= 0; bin--) {
            unsigned c = hist[bin];
            if (cum + c >= need) { s_need = need - cum; s_pref = (unsigned)bin; break; }
            cum += c;
        }
    }
    __syncthreads();
    unsigned pref = s_pref;
    hist[tid] = 0;
    __syncthreads();
    for (int i = tid; i < 4096; i += 256) {
        unsigned u = su[i];
        if ((u >> 8) == pref) atomicAdd(&hist[u & 255], 1);
    }
    __syncthreads();
    if (tid == 0) {
        unsigned cum = 0, need = s_need;
        for (int bin = 255; bin >= 0; bin--) {
            unsigned c = hist[bin];
            if (cum + c >= need) { s_need = need - cum; s_pref = (pref << 8) | (unsigned)bin; break; }
            cum += c;
        }
    }
    __syncthreads();
    unsigned tu = s_pref, need = s_need;
    double acc = 0.0;
    for (int i = tid; i < 4096; i += 256) {
        unsigned u = su[i];
        if (u > tu) acc += (double)sort2h(u);
    }
    red[tid] = acc;
    __syncthreads();
    for (int t = 128; t > 0; t >>= 1) {
        if (tid < t) red[tid] += red[tid + t];
        __syncthreads();
    }
    if (tid == 0)
        g_kreduce[bd] = (float)((red[0] + (double)need * (double)sort2h(tu)) / (double)LSEL);
}

__global__ void k_meanfin() {
    int b = blockIdx.x, d = threadIdx.x;
    double s = 0.0;
    for (int j = 0; j < 128; j++) s += g_meanpart[((size_t)b * 128 + j) * D_ + d];
    g_meanvals[b * D_ + d] = (float)(s / (double)LK);
}

// =================== sqk = Q . K_reduce (fp64) ===============================
__global__ void k_sqk(const float* __restrict__ queries) {
    __shared__ float kr[D_];
    int warp = threadIdx.x >> 5, lane = threadIdx.x & 31;
    int qflat = blockIdx.x * 8 + warp;
    int b = qflat >> 12;
    for (int i = threadIdx.x; i < D_; i += 256) kr[i] = g_kreduce[b * D_ + i];
    __syncthreads();
    const float* qp = queries + (size_t)qflat * D_;
    double acc = 0.0;
#pragma unroll
    for (int j = 0; j < 16; j++) {
        int d = lane + 32 * j;
        acc += (double)qp[d] * (double)kr[d];
    }
    for (int off = 16; off; off >>= 1) acc += __shfl_down_sync(0xffffffffu, acc, off);
    if (lane == 0) g_sqk[qflat] = (float)acc;
}

// ============ threshold + compaction (fused, exact 32-bit radix, 1024t) =====
__global__ void k_thresh() {
    __shared__ unsigned su[4096];
    __shared__ unsigned hist[256];
    __shared__ unsigned s_pref, s_need;
    int b = blockIdx.x, tid = threadIdx.x;
    if (tid == 0) { s_pref = 0; s_need = LSEL; g_selcnt[b] = 0; }
    __syncthreads();
    for (int i = tid; i < 4096; i += 1024) su[i] = f2sort(g_sqk[b * LQ + i]);
    __syncthreads();
    unsigned pref = 0, need = LSEL;
    for (int pass = 3; pass >= 0; pass--) {
        if (tid < 256) hist[tid] = 0;
        __syncthreads();
        for (int i = tid; i < 4096; i += 1024) {
            unsigned u = su[i];
            unsigned hi = (pass == 3) ? 0u : (u >> ((pass + 1) * 8));
            if (hi == pref) atomicAdd(&hist[(u >> (pass * 8)) & 255], 1);
        }
        __syncthreads();
        if (tid == 0) {
            unsigned cum = 0;
            for (int bin = 255; bin >= 0; bin--) {
                unsigned c = hist[bin];
                if (cum + c >= need) {
                    s_need = need - cum;
                    s_pref = (pref << 8) | (unsigned)bin;
                    break;
                }
                cum += c;
            }
        }
        __syncthreads();
        pref = s_pref; need = s_need;
        __syncthreads();
    }
    unsigned tu = s_pref;
    if (tid == 0) g_thresh[b] = sort2f(tu);
    for (int i = tid; i < 4096; i += 1024) {
        if (su[i] >= tu) {
            int pos = atomicAdd(&g_selcnt[b], 1);
            if (pos < LSEL) g_selidx[b * LSEL + pos] = i;
        }
    }
}

__global__ void k_fill(float* __restrict__ out) {
    int r = blockIdx.x, b = r >> 12;
    if (g_sqk[r] < g_thresh[b]) {
        const float4* mv = (const float4*)(g_meanvals + b * D_);
        float4* op = (float4*)(out + (size_t)r * D_);
        op[threadIdx.x] = mv[threadIdx.x];
    }
}

// =================== 1-pass fp16 tile compute (128x128, warp 32x64) =========
__device__ __forceinline__ void gemm_stage1(uint32_t st, int wm, int wn, int lane,
                                            float d[2][8][4]) {
    int rA = wm * 32 + (lane & 15);
    int kA = (lane >> 4) * 16;
    int rB = wn * 64 + (lane & 7) + ((lane >> 4) << 3);
    int kB = ((lane >> 3) & 1) * 16;
#pragma unroll
    for (int t = 0; t < 4; t++) {
        uint32_t a0[4], a1[4];
        LDSM4(a0, swaddr(st, rA, t * 32 + kA));
        LDSM4(a1, swaddr(st, rA + 16, t * 32 + kA));
#pragma unroll
        for (int p = 0; p < 4; p++) {
            uint32_t bh[4];
            LDSM4(bh, swaddr(st + 16384, rB + p * 16, t * 32 + kB));
            MMAH(d[0][2 * p],     a0, bh[0], bh[1]);
            MMAH(d[0][2 * p + 1], a0, bh[2], bh[3]);
            MMAH(d[1][2 * p],     a1, bh[0], bh[1]);
            MMAH(d[1][2 * p + 1], a1, bh[2], bh[3]);
        }
    }
}

#define SMEM_DYN (3 * 32768 + 1024)

// =================== GEMM 1: E = exp(Qsel@K^T) -> tiled, Z partials =========
__global__ void __launch_bounds__(256, 2) k_gemm_qk() {
    extern __shared__ char dsm[];
    __shared__ float zsh[2][128];
    __shared__ alignas(8) unsigned long long mb[3];
    uint32_t sb = (smem_u32(dsm) + 1023) & ~1023u;
    int tid = threadIdx.x;
    int b = blockIdx.z, mt = blockIdx.y, nt = blockIdx.x;
    int m0 = mt * 128, n0 = nt * 128;

    if (tid == 0)
        for (int s = 0; s < 3; s++) MBAR_INIT(smem_u32(&mb[s]), 1);
    __syncthreads();

    const char* srcA = (const char*)g_qsel_t + (((size_t)(b * MT + mt) * 8) << 14);
    const char* srcB = (const char*)g_kh_t + (((size_t)(b * 32 + nt) * 8) << 14);

    if (tid == 0) {
        for (int s = 0; s < 3; s++) {
            uint32_t mba = smem_u32(&mb[s]);
            MBAR_EXPECT(mba, 32768);
            BULK16K(sb + s * 32768, srcA + ((size_t)s << 14), mba);
            BULK16K(sb + s * 32768 + 16384, srcB + ((size_t)s << 14), mba);
        }
    }

    int lane = tid & 31, w = tid >> 5, wm = w >> 1, wn = w & 1;
    float d[2][8][4] = {};

    for (int k = 0; k < 8; k++) {
        int s = k % 3, ph = (k / 3) & 1;
        MBAR_WAIT(smem_u32(&mb[s]), ph);
        gemm_stage1(sb + s * 32768, wm, wn, lane, d);
        __syncthreads();
        if (k + 3 < 8 && tid == 0) {
            uint32_t mba = smem_u32(&mb[s]);
            MBAR_EXPECT(mba, 32768);
            BULK16K(sb + s * 32768, srcA + ((size_t)(k + 3) << 14), mba);
            BULK16K(sb + s * 32768 + 16384, srcB + ((size_t)(k + 3) << 14), mba);
        }
    }

    float rs[2][2] = {};
#pragma unroll
    for (int i = 0; i < 2; i++)
#pragma unroll
        for (int j = 0; j < 8; j++) {
            d[i][j][0] = __expf(d[i][j][0]);
            d[i][j][1] = __expf(d[i][j][1]);
            d[i][j][2] = __expf(d[i][j][2]);
            d[i][j][3] = __expf(d[i][j][3]);
            rs[i][0] += d[i][j][0] + d[i][j][1];
            rs[i][1] += d[i][j][2] + d[i][j][3];
        }
#pragma unroll
    for (int i = 0; i < 2; i++)
#pragma unroll
        for (int h = 0; h < 2; h++) {
            rs[i][h] += __shfl_xor_sync(0xffffffffu, rs[i][h], 1);
            rs[i][h] += __shfl_xor_sync(0xffffffffu, rs[i][h], 2);
        }
    if ((lane & 3) == 0) {
        int rl = wm * 32 + (lane >> 2);
        zsh[wn][rl]      = rs[0][0];
        zsh[wn][rl + 8]  = rs[0][1];
        zsh[wn][rl + 16] = rs[1][0];
        zsh[wn][rl + 24] = rs[1][1];
    }

    // store E into tiled-swizzled layout
    char* tbase = (char*)g_E_t + (((size_t)(b * MT + mt) * 64) << 14);
    int mBase = m0 + wm * 32, nBase = n0 + wn * 64;
#pragma unroll
    for (int i = 0; i < 2; i++) {
        int r = mBase + i * 16 + (lane >> 2);
        int rl = r & 127;
#pragma unroll
        for (int j = 0; j < 8; j++) {
            int c = nBase + j * 8 + (lane & 3) * 2;
            char* tb = tbase + ((size_t)(c >> 6) << 14);
            if (r < LSEL)
                *(__half2*)(tb + swz((uint32_t)(rl * 128 + (c & 63) * 2))) =
                    __floats2half2_rn(d[i][j][0], d[i][j][1]);
            if (r + 8 < LSEL)
                *(__half2*)(tb + swz((uint32_t)((rl + 8) * 128 + (c & 63) * 2))) =
                    __floats2half2_rn(d[i][j][2], d[i][j][3]);
        }
    }
    __syncthreads();
    if (tid < 128) {
        float z = zsh[0][tid] + zsh[1][tid];
        g_Zpart[(size_t)(b * MPAD + m0 + tid) * 32 + nt] = z;
    }
}

// =================== GEMM 2: O = (E @ V)/Z, scatter, Z folded ===============
__global__ void __launch_bounds__(256, 2) k_gemm_pv(float* __restrict__ out) {
    extern __shared__ char dsm[];
    __shared__ int srow[128];
    __shared__ float zrow[128];
    __shared__ alignas(8) unsigned long long mb[3];
    uint32_t sb = (smem_u32(dsm) + 1023) & ~1023u;
    int tid = threadIdx.x;
    int b = blockIdx.z, mt = blockIdx.y, nt = blockIdx.x;
    int m0 = mt * 128, n0 = nt * 128;

    if (tid < 128) {
        int m = m0 + tid;
        srow[tid] = g_selidx[b * LSEL + (m < LSEL ? m : 0)];
    }
    if (tid == 0)
        for (int s = 0; s < 3; s++) MBAR_INIT(smem_u32(&mb[s]), 1);
    __syncthreads();

    const char* srcA = (const char*)g_E_t + (((size_t)(b * MT + mt) * 64) << 14);
    const char* srcB = (const char*)g_vt_t + (((size_t)(b * 4 + nt) * 64) << 14);

    if (tid == 0) {
        for (int s = 0; s < 3; s++) {
            uint32_t mba = smem_u32(&mb[s]);
            MBAR_EXPECT(mba, 32768);
            BULK16K(sb + s * 32768, srcA + ((size_t)s << 14), mba);
            BULK16K(sb + s * 32768 + 16384, srcB + ((size_t)s << 14), mba);
        }
    }

    int lane = tid & 31, w = tid >> 5, wm = w >> 1, wn = w & 1;
    float d[2][8][4] = {};

    for (int k = 0; k < 64; k++) {
        int s = k % 3, ph = (k / 3) & 1;
        MBAR_WAIT(smem_u32(&mb[s]), ph);
        gemm_stage1(sb + s * 32768, wm, wn, lane, d);
        __syncthreads();
        if (k + 3 < 64 && tid == 0) {
            uint32_t mba = smem_u32(&mb[s]);
            MBAR_EXPECT(mba, 32768);
            BULK16K(sb + s * 32768, srcA + ((size_t)(k + 3) << 14), mba);
            BULK16K(sb + s * 32768 + 16384, srcB + ((size_t)(k + 3) << 14), mba);
        }
    }

    if (tid < 128) {
        const float* p = g_Zpart + (size_t)(b * MPAD + m0 + tid) * 32;
        float s = 0.f;
#pragma unroll
        for (int i = 0; i < 32; i++) s += p[i];
        zrow[tid] = s;
    }
    __syncthreads();

    int nBase = n0 + wn * 64;
#pragma unroll
    for (int i = 0; i < 2; i++) {
        int lr = wm * 32 + i * 16 + (lane >> 2);
        int m = m0 + lr;
        float zi0 = 1.0f / zrow[lr];
        float zi1 = 1.0f / zrow[lr + 8];
        int q0 = srow[lr], q1 = srow[lr + 8];
#pragma unroll
        for (int j = 0; j < 8; j++) {
            int c = nBase + j * 8 + (lane & 3) * 2;
            if (m < LSEL)
                *(float2*)(out + ((size_t)b * LQ + q0) * D_ + c) =
                    float2{d[i][j][0] * zi0, d[i][j][1] * zi0};
            if (m + 8 < LSEL)
                *(float2*)(out + ((size_t)b * LQ + q1) * D_ + c) =
                    float2{d[i][j][2] * zi1, d[i][j][3] * zi1};
        }
    }
}

// =================== streams/events (created at static init, pre-capture) ==
static cudaStream_t hx_sb = nullptr;
static cudaEvent_t hx_ev0, hx_evQ, hx_evV, hx_evB, hx_evJ;
static void hx_init() {
    if (!hx_sb) {
        cudaStreamCreateWithFlags(&hx_sb, cudaStreamNonBlocking);
        cudaEventCreateWithFlags(&hx_ev0, cudaEventDisableTiming);
        cudaEventCreateWithFlags(&hx_evQ, cudaEventDisableTiming);
        cudaEventCreateWithFlags(&hx_evV, cudaEventDisableTiming);
        cudaEventCreateWithFlags(&hx_evB, cudaEventDisableTiming);
        cudaEventCreateWithFlags(&hx_evJ, cudaEventDisableTiming);
    }
}
static struct HxInit { HxInit() { hx_init(); } } hx_init_obj;

// =================== launch ==================================================
extern "C" void kernel_launch(void* const* d_in, const int* in_sizes, int n_in,
                              void* d_out, int out_size) {
    const float* q = (const float*)d_in[0];
    const float* k = (const float*)d_in[1];
    const float* v = (const float*)d_in[2];
    float* out = (float*)d_out;

    hx_init();
    cudaFuncSetAttribute(k_gemm_qk, cudaFuncAttributeMaxDynamicSharedMemorySize, SMEM_DYN);
    cudaFuncSetAttribute(k_gemm_pv, cudaFuncAttributeMaxDynamicSharedMemorySize, SMEM_DYN);

    // fork side stream
    cudaEventRecord(hx_ev0, 0);
    cudaStreamWaitEvent(hx_sb, hx_ev0, 0);

    // side: K fp16 tiles, V prep, means
    k_prep_kh<<<8192, 256, 0, hx_sb>>>((const float4*)k);
    cudaEventRecord(hx_evQ, hx_sb);
    k_prep_v<<<dim3(16, 128, 8), dim3(32, 8), 0, hx_sb>>>(v);
    k_meanfin<<<B_, 512, 0, hx_sb>>>();
    cudaEventRecord(hx_evV, hx_sb);

    // main: selection critical path
    k_prep_kt<<<dim3(16, 128, 8), dim3(32, 8)>>>(k);
    k_kreduce<<<B_ * D_, 256>>>();
    k_sqk<<<B_ * LQ / 8, 256>>>(q);
    k_thresh<<<B_, 1024>>>();
    cudaEventRecord(hx_evB, 0);

    // side: fill unselected rows; overlaps gather/QK/PV
    cudaStreamWaitEvent(hx_sb, hx_evB, 0);
    k_fill<<<B_ * LQ, 128, 0, hx_sb>>>(out);
    cudaEventRecord(hx_evJ, hx_sb);

    // main: gather Q (needs selidx), then QK (needs kh tiles)
    k_gather_q<<<B_ * MPAD, 128>>>((const float4*)q);
    cudaStreamWaitEvent(0, hx_evQ, 0);
    dim3 g1(32, MT, B_);
    k_gemm_qk<<<g1, 256, SMEM_DYN>>>();

    // main: PV (needs E/Zpart + vt tiles)
    cudaStreamWaitEvent(0, hx_evV, 0);
    dim3 g2(4, MT, B_);
    k_gemm_pv<<<g2, 256, SMEM_DYN>>>(out);

    cudaStreamWaitEvent(0, hx_evJ, 0);
}